// round 1
// baseline (speedup 1.0000x reference)
#include <cuda_runtime.h>
#include <cuda_fp16.h>
#include <math.h>
#include <stdint.h>

// Problem constants
#define S_LEN 4096
#define BATCH 4
#define DM    1024
#define MTOT  (BATCH * S_LEN)   // 16384 rows total

// ---------------------------------------------------------------------------
// Scratch (device globals; no dynamic allocation allowed)
// fp16 split representation: x = hi + lo, each fp16. ~276 MB total.
// ---------------------------------------------------------------------------
__device__ __half g_x1h[(size_t)MTOT * DM];
__device__ __half g_x1l[(size_t)MTOT * DM];
__device__ __half g_x2h[(size_t)MTOT * DM];
__device__ __half g_x2l[(size_t)MTOT * DM];
__device__ __half g_w1h[(size_t)DM * DM];
__device__ __half g_w1l[(size_t)DM * DM];
__device__ __half g_w2h[(size_t)DM * DM];
__device__ __half g_w2l[(size_t)DM * DM];
__device__ __half g_hh[(size_t)MTOT * DM];   // H = hidden@w1+b1, hi part
__device__ __half g_hl[(size_t)MTOT * DM];   // H lo part
__device__ __half g_ih[(size_t)MTOT * DM];   // I = (hidden+pre)@w2+b2, hi
__device__ __half g_il[(size_t)MTOT * DM];   // I lo

// ---------------------------------------------------------------------------
// PTX helpers
// ---------------------------------------------------------------------------
__device__ __forceinline__ void ldsm4(uint32_t addr, uint32_t& r0, uint32_t& r1,
                                      uint32_t& r2, uint32_t& r3) {
    asm volatile("ldmatrix.sync.aligned.m8n8.x4.shared.b16 {%0,%1,%2,%3}, [%4];\n"
                 : "=r"(r0), "=r"(r1), "=r"(r2), "=r"(r3) : "r"(addr));
}
__device__ __forceinline__ void ldsm4t(uint32_t addr, uint32_t& r0, uint32_t& r1,
                                       uint32_t& r2, uint32_t& r3) {
    asm volatile("ldmatrix.sync.aligned.m8n8.x4.trans.shared.b16 {%0,%1,%2,%3}, [%4];\n"
                 : "=r"(r0), "=r"(r1), "=r"(r2), "=r"(r3) : "r"(addr));
}
__device__ __forceinline__ void mma16816(float c[4], const uint32_t a[4],
                                         const uint32_t b[2]) {
    asm volatile(
        "mma.sync.aligned.m16n8k16.row.col.f32.f16.f16.f32 "
        "{%0,%1,%2,%3}, {%4,%5,%6,%7}, {%8,%9}, {%0,%1,%2,%3};\n"
        : "+f"(c[0]), "+f"(c[1]), "+f"(c[2]), "+f"(c[3])
        : "r"(a[0]), "r"(a[1]), "r"(a[2]), "r"(a[3]), "r"(b[0]), "r"(b[1]));
}

__device__ __forceinline__ uint32_t smem_u32(const void* p) {
    return (uint32_t)__cvta_generic_to_shared(p);
}

// ---------------------------------------------------------------------------
// Kernel 1: split hidden and hidden+pre_emb into fp16 hi/lo
// ---------------------------------------------------------------------------
__global__ __launch_bounds__(256) void split_x_kernel(
    const float* __restrict__ hidden, const float* __restrict__ pre) {
    size_t i = ((size_t)blockIdx.x * 256 + threadIdx.x) * 4;
    float4 hv = *(const float4*)(hidden + i);
    float4 pv = *(const float4*)(pre + i);
    float x1[4] = {hv.x, hv.y, hv.z, hv.w};
    float x2[4] = {hv.x + pv.x, hv.y + pv.y, hv.z + pv.z, hv.w + pv.w};
    __half h1[4], l1[4], h2[4], l2[4];
#pragma unroll
    for (int j = 0; j < 4; j++) {
        h1[j] = __float2half_rn(x1[j]);
        l1[j] = __float2half_rn(x1[j] - __half2float(h1[j]));
        h2[j] = __float2half_rn(x2[j]);
        l2[j] = __float2half_rn(x2[j] - __half2float(h2[j]));
    }
#pragma unroll
    for (int j = 0; j < 2; j++) {
        *(__half2*)(g_x1h + i + 2 * j) = __halves2half2(h1[2 * j], h1[2 * j + 1]);
        *(__half2*)(g_x1l + i + 2 * j) = __halves2half2(l1[2 * j], l1[2 * j + 1]);
        *(__half2*)(g_x2h + i + 2 * j) = __halves2half2(h2[2 * j], h2[2 * j + 1]);
        *(__half2*)(g_x2l + i + 2 * j) = __halves2half2(l2[2 * j], l2[2 * j + 1]);
    }
}

// ---------------------------------------------------------------------------
// Kernel 2: split weights
// ---------------------------------------------------------------------------
__global__ __launch_bounds__(256) void split_w_kernel(
    const float* __restrict__ w1, const float* __restrict__ w2) {
    size_t i = ((size_t)blockIdx.x * 256 + threadIdx.x) * 4;
    float4 v1 = *(const float4*)(w1 + i);
    float4 v2 = *(const float4*)(w2 + i);
    float a1[4] = {v1.x, v1.y, v1.z, v1.w};
    float a2[4] = {v2.x, v2.y, v2.z, v2.w};
#pragma unroll
    for (int j = 0; j < 4; j++) {
        __half h1 = __float2half_rn(a1[j]);
        __half l1 = __float2half_rn(a1[j] - __half2float(h1));
        __half h2 = __float2half_rn(a2[j]);
        __half l2 = __float2half_rn(a2[j] - __half2float(h2));
        g_w1h[i + j] = h1; g_w1l[i + j] = l1;
        g_w2h[i + j] = h2; g_w2l[i + j] = l2;
    }
}

// ---------------------------------------------------------------------------
// Kernel 3: GEMM1 — C[16384,1024] = X[16384,1024] @ W[1024,1024] + bias,
// fp16-split x3 emulation. blockIdx.z selects (x1,w1,b1 -> H) vs (x2,w2,b2 -> I).
// Epilogue re-splits the fp32 result into fp16 hi/lo for stage 2.
// B (W) is row-major [K][N] -> smem [k][n], ldmatrix.trans for B frags.
// ---------------------------------------------------------------------------
__global__ __launch_bounds__(256) void gemm1_kernel(
    const float* __restrict__ bias1, const float* __restrict__ bias2) {
    __shared__ __half sAh[128 * 40], sAl[128 * 40];
    __shared__ __half sBh[32 * 136], sBl[32 * 136];

    const int tid = threadIdx.x, lane = tid & 31, warp = tid >> 5;
    const int wm = warp >> 1, wn = warp & 1;
    const int bm = blockIdx.y * 128, bn = blockIdx.x * 128;

    const __half *Ah, *Al, *Bh, *Bl;
    __half *Ch, *Cl;
    const float* bias;
    if (blockIdx.z == 0) {
        Ah = g_x1h; Al = g_x1l; Bh = g_w1h; Bl = g_w1l;
        Ch = g_hh; Cl = g_hl; bias = bias1;
    } else {
        Ah = g_x2h; Al = g_x2l; Bh = g_w2h; Bl = g_w2l;
        Ch = g_ih; Cl = g_il; bias = bias2;
    }

    float acc[2][8][4];
#pragma unroll
    for (int mi = 0; mi < 2; mi++)
#pragma unroll
        for (int ni = 0; ni < 8; ni++)
#pragma unroll
            for (int j = 0; j < 4; j++) acc[mi][ni][j] = 0.f;

    for (int k0 = 0; k0 < DM; k0 += 32) {
        // Load A tiles: 128 rows x 32 halves; 512 uint4 slots, 2 per thread.
#pragma unroll
        for (int s = 0; s < 2; s++) {
            int slot = tid + s * 256;
            int row = slot >> 2, cg = slot & 3;
            size_t g = (size_t)(bm + row) * DM + k0 + cg * 8;
            *(uint4*)(sAh + row * 40 + cg * 8) = *(const uint4*)(Ah + g);
            *(uint4*)(sAl + row * 40 + cg * 8) = *(const uint4*)(Al + g);
        }
        // Load B tiles: W rows k0..k0+32, cols bn..bn+128 -> smem [k][n].
#pragma unroll
        for (int s = 0; s < 2; s++) {
            int slot = tid + s * 256;
            int row = slot >> 4, cg = slot & 15;
            size_t g = (size_t)(k0 + row) * DM + bn + cg * 8;
            *(uint4*)(sBh + row * 136 + cg * 8) = *(const uint4*)(Bh + g);
            *(uint4*)(sBl + row * 136 + cg * 8) = *(const uint4*)(Bl + g);
        }
        __syncthreads();

#pragma unroll
        for (int p = 0; p < 3; p++) {
            const __half* sA = (p == 2) ? sAl : sAh;
            const __half* sB = (p == 1) ? sBl : sBh;
#pragma unroll
            for (int kk = 0; kk < 32; kk += 16) {
                uint32_t a[2][4];
                const int g = lane >> 3;
#pragma unroll
                for (int mi = 0; mi < 2; mi++) {
                    int row = wm * 32 + mi * 16 + (lane & 7) + (g & 1) * 8;
                    int col = kk + (g >> 1) * 8;
                    ldsm4(smem_u32(sA + row * 40 + col),
                          a[mi][0], a[mi][1], a[mi][2], a[mi][3]);
                }
                uint32_t b[8][2];
#pragma unroll
                for (int ng = 0; ng < 4; ng++) {
                    int krow = kk + (lane & 7) + (g & 1) * 8;
                    int col = wn * 64 + ng * 16 + (g >> 1) * 8;
                    uint32_t r0, r1, r2, r3;
                    ldsm4t(smem_u32(sB + krow * 136 + col), r0, r1, r2, r3);
                    b[2 * ng][0] = r0; b[2 * ng][1] = r1;
                    b[2 * ng + 1][0] = r2; b[2 * ng + 1][1] = r3;
                }
#pragma unroll
                for (int mi = 0; mi < 2; mi++)
#pragma unroll
                    for (int ni = 0; ni < 8; ni++)
                        mma16816(acc[mi][ni], a[mi], b[ni]);
            }
        }
        __syncthreads();
    }

    // Epilogue: add bias, split to fp16 hi/lo, store.
#pragma unroll
    for (int mi = 0; mi < 2; mi++) {
#pragma unroll
        for (int ni = 0; ni < 8; ni++) {
            int col = bn + wn * 64 + ni * 8 + 2 * (lane & 3);
            float2 bv = *(const float2*)(bias + col);
#pragma unroll
            for (int h = 0; h < 2; h++) {
                int row = bm + wm * 32 + mi * 16 + (lane >> 2) + h * 8;
                float v0 = acc[mi][ni][2 * h + 0] + bv.x;
                float v1 = acc[mi][ni][2 * h + 1] + bv.y;
                __half h0 = __float2half_rn(v0), h1 = __float2half_rn(v1);
                __half l0 = __float2half_rn(v0 - __half2float(h0));
                __half l1 = __float2half_rn(v1 - __half2float(h1));
                *(__half2*)(Ch + (size_t)row * DM + col) = __halves2half2(h0, h1);
                *(__half2*)(Cl + (size_t)row * DM + col) = __halves2half2(l0, l1);
            }
        }
    }
}

// ---------------------------------------------------------------------------
// Kernel 4: GEMM2 — logits[b,q,k] = sum_e H[b,q,e] * I[b,k,e]  (H @ I^T)
// Both operands row-major [S][D]; B tile stored [n][k] like A, non-trans
// ldmatrix for B frags. fp16-split x3. Writes fp32 logits into d_out.
// ---------------------------------------------------------------------------
__global__ __launch_bounds__(256) void gemm2_kernel(float* __restrict__ out) {
    __shared__ __half sAh[128 * 40], sAl[128 * 40];
    __shared__ __half sBh[128 * 40], sBl[128 * 40];

    const int tid = threadIdx.x, lane = tid & 31, warp = tid >> 5;
    const int wm = warp >> 1, wn = warp & 1;
    const int bq = blockIdx.y * 128, bk = blockIdx.x * 128;
    const int bat = blockIdx.z;

    const __half* Ah = g_hh + (size_t)bat * S_LEN * DM;
    const __half* Al = g_hl + (size_t)bat * S_LEN * DM;
    const __half* Bh = g_ih + (size_t)bat * S_LEN * DM;
    const __half* Bl = g_il + (size_t)bat * S_LEN * DM;

    float acc[2][8][4];
#pragma unroll
    for (int mi = 0; mi < 2; mi++)
#pragma unroll
        for (int ni = 0; ni < 8; ni++)
#pragma unroll
            for (int j = 0; j < 4; j++) acc[mi][ni][j] = 0.f;

    for (int k0 = 0; k0 < DM; k0 += 32) {
#pragma unroll
        for (int s = 0; s < 2; s++) {
            int slot = tid + s * 256;
            int row = slot >> 2, cg = slot & 3;
            size_t ga = (size_t)(bq + row) * DM + k0 + cg * 8;
            size_t gb = (size_t)(bk + row) * DM + k0 + cg * 8;
            *(uint4*)(sAh + row * 40 + cg * 8) = *(const uint4*)(Ah + ga);
            *(uint4*)(sAl + row * 40 + cg * 8) = *(const uint4*)(Al + ga);
            *(uint4*)(sBh + row * 40 + cg * 8) = *(const uint4*)(Bh + gb);
            *(uint4*)(sBl + row * 40 + cg * 8) = *(const uint4*)(Bl + gb);
        }
        __syncthreads();

#pragma unroll
        for (int p = 0; p < 3; p++) {
            const __half* sA = (p == 2) ? sAl : sAh;
            const __half* sB = (p == 1) ? sBl : sBh;
#pragma unroll
            for (int kk = 0; kk < 32; kk += 16) {
                const int g = lane >> 3;
                uint32_t a[2][4];
#pragma unroll
                for (int mi = 0; mi < 2; mi++) {
                    int row = wm * 32 + mi * 16 + (lane & 7) + (g & 1) * 8;
                    int col = kk + (g >> 1) * 8;
                    ldsm4(smem_u32(sA + row * 40 + col),
                          a[mi][0], a[mi][1], a[mi][2], a[mi][3]);
                }
                uint32_t b[8][2];
#pragma unroll
                for (int ng = 0; ng < 4; ng++) {
                    int row = wn * 64 + ng * 16 + (lane & 7) + (g & 1) * 8;
                    int col = kk + (g >> 1) * 8;
                    uint32_t r0, r1, r2, r3;
                    ldsm4(smem_u32(sB + row * 40 + col), r0, r1, r2, r3);
                    b[2 * ng][0] = r0; b[2 * ng][1] = r2;   // n 0-7 of group
                    b[2 * ng + 1][0] = r1; b[2 * ng + 1][1] = r3; // n 8-15
                }
#pragma unroll
                for (int mi = 0; mi < 2; mi++)
#pragma unroll
                    for (int ni = 0; ni < 8; ni++)
                        mma16816(acc[mi][ni], a[mi], b[ni]);
            }
        }
        __syncthreads();
    }

    float* obase = out + (size_t)bat * S_LEN * S_LEN;
#pragma unroll
    for (int mi = 0; mi < 2; mi++) {
#pragma unroll
        for (int ni = 0; ni < 8; ni++) {
            int col = bk + wn * 64 + ni * 8 + 2 * (lane & 3);
#pragma unroll
            for (int h = 0; h < 2; h++) {
                int row = bq + wm * 32 + mi * 16 + (lane >> 2) + h * 8;
                float2 v = make_float2(acc[mi][ni][2 * h + 0],
                                       acc[mi][ni][2 * h + 1]);
                *(float2*)(obase + (size_t)row * S_LEN + col) = v;
            }
        }
    }
}

// ---------------------------------------------------------------------------
// Kernel 5: rowwise softmax in place over d_out (16384 rows x 4096)
// ---------------------------------------------------------------------------
__global__ __launch_bounds__(256) void softmax_kernel(float* __restrict__ out) {
    __shared__ float red[8];
    const int t = threadIdx.x, lane = t & 31, warp = t >> 5;
    float* p = out + (size_t)blockIdx.x * S_LEN;

    float4 v[4];
#pragma unroll
    for (int i = 0; i < 4; i++) v[i] = *(const float4*)(p + (i * 256 + t) * 4);

    float mx = -INFINITY;
#pragma unroll
    for (int i = 0; i < 4; i++) {
        mx = fmaxf(mx, fmaxf(fmaxf(v[i].x, v[i].y), fmaxf(v[i].z, v[i].w)));
    }
#pragma unroll
    for (int o = 16; o >= 1; o >>= 1)
        mx = fmaxf(mx, __shfl_xor_sync(0xffffffffu, mx, o));
    if (lane == 0) red[warp] = mx;
    __syncthreads();
    float bmx = red[0];
#pragma unroll
    for (int w = 1; w < 8; w++) bmx = fmaxf(bmx, red[w]);
    __syncthreads();

    float sum = 0.f;
#pragma unroll
    for (int i = 0; i < 4; i++) {
        v[i].x = expf(v[i].x - bmx); sum += v[i].x;
        v[i].y = expf(v[i].y - bmx); sum += v[i].y;
        v[i].z = expf(v[i].z - bmx); sum += v[i].z;
        v[i].w = expf(v[i].w - bmx); sum += v[i].w;
    }
#pragma unroll
    for (int o = 16; o >= 1; o >>= 1)
        sum += __shfl_xor_sync(0xffffffffu, sum, o);
    if (lane == 0) red[warp] = sum;
    __syncthreads();
    float bsum = 0.f;
#pragma unroll
    for (int w = 0; w < 8; w++) bsum += red[w];

    float inv = 1.0f / bsum;
#pragma unroll
    for (int i = 0; i < 4; i++) {
        v[i].x *= inv; v[i].y *= inv; v[i].z *= inv; v[i].w *= inv;
        *(float4*)(p + (i * 256 + t) * 4) = v[i];
    }
}

// ---------------------------------------------------------------------------
// Launch
// ---------------------------------------------------------------------------
extern "C" void kernel_launch(void* const* d_in, const int* in_sizes, int n_in,
                              void* d_out, int out_size) {
    (void)in_sizes; (void)n_in; (void)out_size;
    const float* hidden = (const float*)d_in[0];
    const float* pre    = (const float*)d_in[1];
    const float* w1     = (const float*)d_in[2];
    const float* b1     = (const float*)d_in[3];
    const float* w2     = (const float*)d_in[4];
    const float* b2     = (const float*)d_in[5];
    float* out = (float*)d_out;

    split_x_kernel<<<(MTOT * DM) / (256 * 4), 256>>>(hidden, pre);
    split_w_kernel<<<(DM * DM) / (256 * 4), 256>>>(w1, w2);
    gemm1_kernel<<<dim3(DM / 128, MTOT / 128, 2), 256>>>(b1, b2);
    gemm2_kernel<<<dim3(S_LEN / 128, S_LEN / 128, BATCH), 256>>>(out);
    softmax_kernel<<<MTOT, 256>>>(out);
}

// round 2
// speedup vs baseline: 1.0959x; 1.0959x over previous
#include <cuda_runtime.h>
#include <cuda_fp16.h>
#include <math.h>
#include <stdint.h>

// Problem constants
#define S_LEN 4096
#define BATCH 4
#define DM    1024
#define MTOT  (BATCH * S_LEN)   // 16384 rows total

// ---------------------------------------------------------------------------
// Scratch (device globals; no dynamic allocation allowed)
// ---------------------------------------------------------------------------
__device__ __half g_x1h[(size_t)MTOT * DM];
__device__ __half g_x1l[(size_t)MTOT * DM];
__device__ __half g_x2h[(size_t)MTOT * DM];
__device__ __half g_x2l[(size_t)MTOT * DM];
__device__ __half g_w1h[(size_t)DM * DM];
__device__ __half g_w1l[(size_t)DM * DM];
__device__ __half g_w2h[(size_t)DM * DM];
__device__ __half g_w2l[(size_t)DM * DM];
__device__ __half g_hh[(size_t)MTOT * DM];
__device__ __half g_hl[(size_t)MTOT * DM];
__device__ __half g_ih[(size_t)MTOT * DM];
__device__ __half g_il[(size_t)MTOT * DM];

// ---------------------------------------------------------------------------
// PTX helpers
// ---------------------------------------------------------------------------
__device__ __forceinline__ uint32_t smem_u32(const void* p) {
    return (uint32_t)__cvta_generic_to_shared(p);
}
__device__ __forceinline__ void ldsm4(uint32_t addr, uint32_t& r0, uint32_t& r1,
                                      uint32_t& r2, uint32_t& r3) {
    asm volatile("ldmatrix.sync.aligned.m8n8.x4.shared.b16 {%0,%1,%2,%3}, [%4];\n"
                 : "=r"(r0), "=r"(r1), "=r"(r2), "=r"(r3) : "r"(addr));
}
__device__ __forceinline__ void ldsm4t(uint32_t addr, uint32_t& r0, uint32_t& r1,
                                       uint32_t& r2, uint32_t& r3) {
    asm volatile("ldmatrix.sync.aligned.m8n8.x4.trans.shared.b16 {%0,%1,%2,%3}, [%4];\n"
                 : "=r"(r0), "=r"(r1), "=r"(r2), "=r"(r3) : "r"(addr));
}
__device__ __forceinline__ void mma16816(float c[4], const uint32_t a[4],
                                         const uint32_t b[2]) {
    asm volatile(
        "mma.sync.aligned.m16n8k16.row.col.f32.f16.f16.f32 "
        "{%0,%1,%2,%3}, {%4,%5,%6,%7}, {%8,%9}, {%0,%1,%2,%3};\n"
        : "+f"(c[0]), "+f"(c[1]), "+f"(c[2]), "+f"(c[3])
        : "r"(a[0]), "r"(a[1]), "r"(a[2]), "r"(a[3]), "r"(b[0]), "r"(b[1]));
}
__device__ __forceinline__ void cp16(void* sdst, const void* gsrc) {
    uint32_t s = smem_u32(sdst);
    asm volatile("cp.async.cg.shared.global [%0], [%1], 16;\n" :: "r"(s), "l"(gsrc));
}
#define CP_COMMIT() asm volatile("cp.async.commit_group;\n" ::: "memory")
#define CP_WAIT(n)  asm volatile("cp.async.wait_group %0;\n" :: "n"(n) : "memory")

// ---------------------------------------------------------------------------
// Kernel 1: split hidden and hidden+pre_emb into fp16 hi/lo
// ---------------------------------------------------------------------------
__global__ __launch_bounds__(256) void split_x_kernel(
    const float* __restrict__ hidden, const float* __restrict__ pre) {
    size_t i = ((size_t)blockIdx.x * 256 + threadIdx.x) * 4;
    float4 hv = *(const float4*)(hidden + i);
    float4 pv = *(const float4*)(pre + i);
    float x1[4] = {hv.x, hv.y, hv.z, hv.w};
    float x2[4] = {hv.x + pv.x, hv.y + pv.y, hv.z + pv.z, hv.w + pv.w};
    __half h1[4], l1[4], h2[4], l2[4];
#pragma unroll
    for (int j = 0; j < 4; j++) {
        h1[j] = __float2half_rn(x1[j]);
        l1[j] = __float2half_rn(x1[j] - __half2float(h1[j]));
        h2[j] = __float2half_rn(x2[j]);
        l2[j] = __float2half_rn(x2[j] - __half2float(h2[j]));
    }
#pragma unroll
    for (int j = 0; j < 2; j++) {
        *(__half2*)(g_x1h + i + 2 * j) = __halves2half2(h1[2 * j], h1[2 * j + 1]);
        *(__half2*)(g_x1l + i + 2 * j) = __halves2half2(l1[2 * j], l1[2 * j + 1]);
        *(__half2*)(g_x2h + i + 2 * j) = __halves2half2(h2[2 * j], h2[2 * j + 1]);
        *(__half2*)(g_x2l + i + 2 * j) = __halves2half2(l2[2 * j], l2[2 * j + 1]);
    }
}

// ---------------------------------------------------------------------------
// Kernel 2: split weights
// ---------------------------------------------------------------------------
__global__ __launch_bounds__(256) void split_w_kernel(
    const float* __restrict__ w1, const float* __restrict__ w2) {
    size_t i = ((size_t)blockIdx.x * 256 + threadIdx.x) * 4;
    float4 v1 = *(const float4*)(w1 + i);
    float4 v2 = *(const float4*)(w2 + i);
    float a1[4] = {v1.x, v1.y, v1.z, v1.w};
    float a2[4] = {v2.x, v2.y, v2.z, v2.w};
#pragma unroll
    for (int j = 0; j < 4; j++) {
        __half h1 = __float2half_rn(a1[j]);
        __half l1 = __float2half_rn(a1[j] - __half2float(h1));
        __half h2 = __float2half_rn(a2[j]);
        __half l2 = __float2half_rn(a2[j] - __half2float(h2));
        g_w1h[i + j] = h1; g_w1l[i + j] = l1;
        g_w2h[i + j] = h2; g_w2l[i + j] = l2;
    }
}

// ---------------------------------------------------------------------------
// Kernel 3: GEMM1 — C[16384,1024] = X @ W + bias, fp16-split x3.
// 2-stage cp.async pipeline; fragments loaded once per k-chunk.
// Stage layout (halves): sAh[128*40] sAl[128*40] sBh[32*136] sBl[32*136]
// Stage stride = 5120+5120+4352+4352 = 18944 halves.
// ---------------------------------------------------------------------------
#define G1_STAGE 18944
#define G1_SMEM  (2 * G1_STAGE * 2)   // bytes

__global__ __launch_bounds__(256, 1) void gemm1_kernel(
    const float* __restrict__ bias1, const float* __restrict__ bias2) {
    extern __shared__ __half sm1[];

    const int tid = threadIdx.x, lane = tid & 31, warp = tid >> 5;
    const int wm = warp >> 1, wn = warp & 1;
    const int bm = blockIdx.y * 128, bn = blockIdx.x * 128;

    const __half *Ah, *Al, *Bh, *Bl;
    __half *Ch, *Cl;
    const float* bias;
    if (blockIdx.z == 0) {
        Ah = g_x1h; Al = g_x1l; Bh = g_w1h; Bl = g_w1l;
        Ch = g_hh; Cl = g_hl; bias = bias1;
    } else {
        Ah = g_x2h; Al = g_x2l; Bh = g_w2h; Bl = g_w2l;
        Ch = g_ih; Cl = g_il; bias = bias2;
    }

    auto load_slab = [&](int k0, int stage) {
        __half* base = sm1 + stage * G1_STAGE;
#pragma unroll
        for (int s = 0; s < 2; s++) {
            int slot = tid + s * 256;
            int row = slot >> 2, cg = slot & 3;
            size_t g = (size_t)(bm + row) * DM + k0 + cg * 8;
            int so = row * 40 + cg * 8;
            cp16(base + so, Ah + g);
            cp16(base + 5120 + so, Al + g);
        }
#pragma unroll
        for (int s = 0; s < 2; s++) {
            int slot = tid + s * 256;
            int row = slot >> 4, cg = slot & 15;
            size_t g = (size_t)(k0 + row) * DM + bn + cg * 8;
            int so = row * 136 + cg * 8;
            cp16(base + 10240 + so, Bh + g);
            cp16(base + 14592 + so, Bl + g);
        }
        CP_COMMIT();
    };

    float acc[2][8][4];
#pragma unroll
    for (int mi = 0; mi < 2; mi++)
#pragma unroll
        for (int ni = 0; ni < 8; ni++)
#pragma unroll
            for (int j = 0; j < 4; j++) acc[mi][ni][j] = 0.f;

    load_slab(0, 0);

    for (int it = 0; it < DM / 32; it++) {
        const int stage = it & 1;
        if (it + 1 < DM / 32) { load_slab((it + 1) * 32, stage ^ 1); CP_WAIT(1); }
        else                  { CP_WAIT(0); }
        __syncthreads();

        const __half* sAh = sm1 + stage * G1_STAGE;
        const __half* sAl = sAh + 5120;
        const __half* sBh = sAh + 10240;
        const __half* sBl = sAh + 14592;

#pragma unroll
        for (int kk = 0; kk < 32; kk += 16) {
            const int g = lane >> 3;
            uint32_t ah[2][4], al[2][4];
#pragma unroll
            for (int mi = 0; mi < 2; mi++) {
                int row = wm * 32 + mi * 16 + (lane & 7) + (g & 1) * 8;
                int col = kk + (g >> 1) * 8;
                ldsm4(smem_u32(sAh + row * 40 + col),
                      ah[mi][0], ah[mi][1], ah[mi][2], ah[mi][3]);
                ldsm4(smem_u32(sAl + row * 40 + col),
                      al[mi][0], al[mi][1], al[mi][2], al[mi][3]);
            }
            uint32_t bh[8][2], bl[8][2];
#pragma unroll
            for (int ng = 0; ng < 4; ng++) {
                int krow = kk + (lane & 7) + (g & 1) * 8;
                int col = wn * 64 + ng * 16 + (g >> 1) * 8;
                uint32_t r0, r1, r2, r3;
                ldsm4t(smem_u32(sBh + krow * 136 + col), r0, r1, r2, r3);
                bh[2 * ng][0] = r0; bh[2 * ng][1] = r1;
                bh[2 * ng + 1][0] = r2; bh[2 * ng + 1][1] = r3;
                ldsm4t(smem_u32(sBl + krow * 136 + col), r0, r1, r2, r3);
                bl[2 * ng][0] = r0; bl[2 * ng][1] = r1;
                bl[2 * ng + 1][0] = r2; bl[2 * ng + 1][1] = r3;
            }
#pragma unroll
            for (int mi = 0; mi < 2; mi++)
#pragma unroll
                for (int ni = 0; ni < 8; ni++) mma16816(acc[mi][ni], ah[mi], bh[ni]);
#pragma unroll
            for (int mi = 0; mi < 2; mi++)
#pragma unroll
                for (int ni = 0; ni < 8; ni++) mma16816(acc[mi][ni], ah[mi], bl[ni]);
#pragma unroll
            for (int mi = 0; mi < 2; mi++)
#pragma unroll
                for (int ni = 0; ni < 8; ni++) mma16816(acc[mi][ni], al[mi], bh[ni]);
        }
        __syncthreads();
    }

    // Epilogue: add bias, split to fp16 hi/lo, store.
#pragma unroll
    for (int mi = 0; mi < 2; mi++) {
#pragma unroll
        for (int ni = 0; ni < 8; ni++) {
            int col = bn + wn * 64 + ni * 8 + 2 * (lane & 3);
            float2 bv = *(const float2*)(bias + col);
#pragma unroll
            for (int h = 0; h < 2; h++) {
                int row = bm + wm * 32 + mi * 16 + (lane >> 2) + h * 8;
                float v0 = acc[mi][ni][2 * h + 0] + bv.x;
                float v1 = acc[mi][ni][2 * h + 1] + bv.y;
                __half h0 = __float2half_rn(v0), h1 = __float2half_rn(v1);
                __half l0 = __float2half_rn(v0 - __half2float(h0));
                __half l1 = __float2half_rn(v1 - __half2float(h1));
                *(__half2*)(Ch + (size_t)row * DM + col) = __halves2half2(h0, h1);
                *(__half2*)(Cl + (size_t)row * DM + col) = __halves2half2(l0, l1);
            }
        }
    }
}

// ---------------------------------------------------------------------------
// Kernel 4: GEMM2 — logits = H @ I^T per batch, fp16-split x3.
// 2-stage cp.async pipeline; fragments loaded once per k-chunk.
// Stage layout (halves): sAh[5120] sAl[5120] sBh[5120] sBl[5120] = 20480.
// ---------------------------------------------------------------------------
#define G2_STAGE 20480
#define G2_SMEM  (2 * G2_STAGE * 2)   // bytes

__global__ __launch_bounds__(256, 1) void gemm2_kernel(float* __restrict__ out) {
    extern __shared__ __half sm2[];

    const int tid = threadIdx.x, lane = tid & 31, warp = tid >> 5;
    const int wm = warp >> 1, wn = warp & 1;
    const int bq = blockIdx.y * 128, bk = blockIdx.x * 128;
    const int bat = blockIdx.z;

    const __half* Ah = g_hh + (size_t)bat * S_LEN * DM;
    const __half* Al = g_hl + (size_t)bat * S_LEN * DM;
    const __half* Bh = g_ih + (size_t)bat * S_LEN * DM;
    const __half* Bl = g_il + (size_t)bat * S_LEN * DM;

    auto load_slab = [&](int k0, int stage) {
        __half* base = sm2 + stage * G2_STAGE;
#pragma unroll
        for (int s = 0; s < 2; s++) {
            int slot = tid + s * 256;
            int row = slot >> 2, cg = slot & 3;
            size_t ga = (size_t)(bq + row) * DM + k0 + cg * 8;
            size_t gb = (size_t)(bk + row) * DM + k0 + cg * 8;
            int so = row * 40 + cg * 8;
            cp16(base + so, Ah + ga);
            cp16(base + 5120 + so, Al + ga);
            cp16(base + 10240 + so, Bh + gb);
            cp16(base + 15360 + so, Bl + gb);
        }
        CP_COMMIT();
    };

    float acc[2][8][4];
#pragma unroll
    for (int mi = 0; mi < 2; mi++)
#pragma unroll
        for (int ni = 0; ni < 8; ni++)
#pragma unroll
            for (int j = 0; j < 4; j++) acc[mi][ni][j] = 0.f;

    load_slab(0, 0);

    for (int it = 0; it < DM / 32; it++) {
        const int stage = it & 1;
        if (it + 1 < DM / 32) { load_slab((it + 1) * 32, stage ^ 1); CP_WAIT(1); }
        else                  { CP_WAIT(0); }
        __syncthreads();

        const __half* sAh = sm2 + stage * G2_STAGE;
        const __half* sAl = sAh + 5120;
        const __half* sBh = sAh + 10240;
        const __half* sBl = sAh + 15360;

#pragma unroll
        for (int kk = 0; kk < 32; kk += 16) {
            const int g = lane >> 3;
            uint32_t ah[2][4], al[2][4];
#pragma unroll
            for (int mi = 0; mi < 2; mi++) {
                int row = wm * 32 + mi * 16 + (lane & 7) + (g & 1) * 8;
                int col = kk + (g >> 1) * 8;
                ldsm4(smem_u32(sAh + row * 40 + col),
                      ah[mi][0], ah[mi][1], ah[mi][2], ah[mi][3]);
                ldsm4(smem_u32(sAl + row * 40 + col),
                      al[mi][0], al[mi][1], al[mi][2], al[mi][3]);
            }
            uint32_t bh[8][2], bl[8][2];
#pragma unroll
            for (int ng = 0; ng < 4; ng++) {
                int row = wn * 64 + ng * 16 + (lane & 7) + (g & 1) * 8;
                int col = kk + (g >> 1) * 8;
                uint32_t r0, r1, r2, r3;
                ldsm4(smem_u32(sBh + row * 40 + col), r0, r1, r2, r3);
                bh[2 * ng][0] = r0; bh[2 * ng][1] = r2;
                bh[2 * ng + 1][0] = r1; bh[2 * ng + 1][1] = r3;
                ldsm4(smem_u32(sBl + row * 40 + col), r0, r1, r2, r3);
                bl[2 * ng][0] = r0; bl[2 * ng][1] = r2;
                bl[2 * ng + 1][0] = r1; bl[2 * ng + 1][1] = r3;
            }
#pragma unroll
            for (int mi = 0; mi < 2; mi++)
#pragma unroll
                for (int ni = 0; ni < 8; ni++) mma16816(acc[mi][ni], ah[mi], bh[ni]);
#pragma unroll
            for (int mi = 0; mi < 2; mi++)
#pragma unroll
                for (int ni = 0; ni < 8; ni++) mma16816(acc[mi][ni], ah[mi], bl[ni]);
#pragma unroll
            for (int mi = 0; mi < 2; mi++)
#pragma unroll
                for (int ni = 0; ni < 8; ni++) mma16816(acc[mi][ni], al[mi], bh[ni]);
        }
        __syncthreads();
    }

    float* obase = out + (size_t)bat * S_LEN * S_LEN;
#pragma unroll
    for (int mi = 0; mi < 2; mi++) {
#pragma unroll
        for (int ni = 0; ni < 8; ni++) {
            int col = bk + wn * 64 + ni * 8 + 2 * (lane & 3);
#pragma unroll
            for (int h = 0; h < 2; h++) {
                int row = bq + wm * 32 + mi * 16 + (lane >> 2) + h * 8;
                float2 v = make_float2(acc[mi][ni][2 * h + 0],
                                       acc[mi][ni][2 * h + 1]);
                *(float2*)(obase + (size_t)row * S_LEN + col) = v;
            }
        }
    }
}

// ---------------------------------------------------------------------------
// Kernel 5: rowwise softmax in place over d_out (16384 rows x 4096)
// ---------------------------------------------------------------------------
__global__ __launch_bounds__(256) void softmax_kernel(float* __restrict__ out) {
    __shared__ float red[8];
    const int t = threadIdx.x, lane = t & 31, warp = t >> 5;
    float* p = out + (size_t)blockIdx.x * S_LEN;

    float4 v[4];
#pragma unroll
    for (int i = 0; i < 4; i++) v[i] = *(const float4*)(p + (i * 256 + t) * 4);

    float mx = -INFINITY;
#pragma unroll
    for (int i = 0; i < 4; i++)
        mx = fmaxf(mx, fmaxf(fmaxf(v[i].x, v[i].y), fmaxf(v[i].z, v[i].w)));
#pragma unroll
    for (int o = 16; o >= 1; o >>= 1)
        mx = fmaxf(mx, __shfl_xor_sync(0xffffffffu, mx, o));
    if (lane == 0) red[warp] = mx;
    __syncthreads();
    float bmx = red[0];
#pragma unroll
    for (int w = 1; w < 8; w++) bmx = fmaxf(bmx, red[w]);
    __syncthreads();

    float sum = 0.f;
#pragma unroll
    for (int i = 0; i < 4; i++) {
        v[i].x = expf(v[i].x - bmx); sum += v[i].x;
        v[i].y = expf(v[i].y - bmx); sum += v[i].y;
        v[i].z = expf(v[i].z - bmx); sum += v[i].z;
        v[i].w = expf(v[i].w - bmx); sum += v[i].w;
    }
#pragma unroll
    for (int o = 16; o >= 1; o >>= 1)
        sum += __shfl_xor_sync(0xffffffffu, sum, o);
    if (lane == 0) red[warp] = sum;
    __syncthreads();
    float bsum = 0.f;
#pragma unroll
    for (int w = 0; w < 8; w++) bsum += red[w];

    float inv = 1.0f / bsum;
#pragma unroll
    for (int i = 0; i < 4; i++) {
        v[i].x *= inv; v[i].y *= inv; v[i].z *= inv; v[i].w *= inv;
        *(float4*)(p + (i * 256 + t) * 4) = v[i];
    }
}

// ---------------------------------------------------------------------------
// Launch
// ---------------------------------------------------------------------------
extern "C" void kernel_launch(void* const* d_in, const int* in_sizes, int n_in,
                              void* d_out, int out_size) {
    (void)in_sizes; (void)n_in; (void)out_size;
    const float* hidden = (const float*)d_in[0];
    const float* pre    = (const float*)d_in[1];
    const float* w1     = (const float*)d_in[2];
    const float* b1     = (const float*)d_in[3];
    const float* w2     = (const float*)d_in[4];
    const float* b2     = (const float*)d_in[5];
    float* out = (float*)d_out;

    cudaFuncSetAttribute(gemm1_kernel,
                         cudaFuncAttributeMaxDynamicSharedMemorySize, G1_SMEM);
    cudaFuncSetAttribute(gemm2_kernel,
                         cudaFuncAttributeMaxDynamicSharedMemorySize, G2_SMEM);

    split_x_kernel<<<(MTOT * DM) / (256 * 4), 256>>>(hidden, pre);
    split_w_kernel<<<(DM * DM) / (256 * 4), 256>>>(w1, w2);
    gemm1_kernel<<<dim3(DM / 128, MTOT / 128, 2), 256, G1_SMEM>>>(b1, b2);
    gemm2_kernel<<<dim3(S_LEN / 128, S_LEN / 128, BATCH), 256, G2_SMEM>>>(out);
    softmax_kernel<<<MTOT, 256>>>(out);
}